// round 10
// baseline (speedup 1.0000x reference)
#include <cuda_runtime.h>
#include <cuda_bf16.h>
#include <cstdint>

// ActuatorNet via warp-level mma.sync (HMMA, bf16 hi/lo 3-term split).
// Round 10 = round 9 verbatim + pairwise-reciprocal softsign in the hidden
// loop. Pipe accounting showed MUFU (32 rcp/warp-layer, rt=8) at ~46% busy,
// co-binding with tensor (~58%) and issue (~50%). Pairwise halves MUFU for
// +1 FMA issue per pair.

#define NTHREADS 256
#define NWARPS   8

typedef unsigned long long u64;

// smem layout (bytes)
#define SM_FRAG   0                      // 19*16*32 u64 = 77824
#define SM_W1     77824                  // 192 f32
#define SM_B1     (SM_W1 + 768)          // 32 f32
#define SM_BH     (SM_B1 + 128)          // 19*32 f32 = 2432
#define SM_WOUT   (SM_BH + 2432)         // 32 f32
#define SM_BOUT   (SM_WOUT + 128)        // 1 f32
#define SM_TOTAL  (SM_BOUT + 16)         // ~81.2 KB -> 2 CTAs/SM

__device__ __forceinline__ uint32_t cvt_bf16x2(float hi_elem, float lo_elem) {
    uint32_t r;
    asm("cvt.rn.bf16x2.f32 %0, %1, %2;" : "=r"(r) : "f"(hi_elem), "f"(lo_elem));
    return r;
}

__device__ __forceinline__ float rcp_fast(float v) {
    float r;
    asm("rcp.approx.f32 %0, %1;" : "=f"(r) : "f"(v));
    return r;
}

// d += a*b
__device__ __forceinline__ void mma_bf16(float* d,
                                         uint32_t a0, uint32_t a1,
                                         uint32_t a2, uint32_t a3,
                                         uint32_t b0, uint32_t b1) {
    asm volatile(
        "mma.sync.aligned.m16n8k16.row.col.f32.bf16.bf16.f32 "
        "{%0,%1,%2,%3}, {%4,%5,%6,%7}, {%8,%9}, {%0,%1,%2,%3};"
        : "+f"(d[0]), "+f"(d[1]), "+f"(d[2]), "+f"(d[3])
        : "r"(a0), "r"(a1), "r"(a2), "r"(a3), "r"(b0), "r"(b1));
}

// d = a*b + {cx,cy,cx,cy}
__device__ __forceinline__ void mma_bf16_init(float* d,
                                              uint32_t a0, uint32_t a1,
                                              uint32_t a2, uint32_t a3,
                                              uint32_t b0, uint32_t b1,
                                              float cx, float cy) {
    asm volatile(
        "mma.sync.aligned.m16n8k16.row.col.f32.bf16.bf16.f32 "
        "{%0,%1,%2,%3}, {%4,%5,%6,%7}, {%8,%9}, {%10,%11,%10,%11};"
        : "=f"(d[0]), "=f"(d[1]), "=f"(d[2]), "=f"(d[3])
        : "r"(a0), "r"(a1), "r"(a2), "r"(a3), "r"(b0), "r"(b1),
          "f"(cx), "f"(cy));
}

__device__ __forceinline__ float softsign_f(float v) {
    return __fdividef(v, 1.0f + fabsf(v));
}

// in-place pairwise-reciprocal softsign over 16 elements (8 rcp, not 16)
__device__ __forceinline__ void softsign16_pairwise(float* a) {
    #pragma unroll
    for (int p = 0; p < 8; p++) {
        float x0 = a[2 * p], x1 = a[2 * p + 1];
        float t0 = 1.0f + fabsf(x0);
        float t1 = 1.0f + fabsf(x1);
        float r = rcp_fast(t0 * t1);
        a[2 * p]     = x0 * t1 * r;
        a[2 * p + 1] = x1 * t0 * r;
    }
}

__device__ __forceinline__ void split_frags(const float* acc,
                                            uint32_t* ahi, uint32_t* alo) {
    #pragma unroll
    for (int p = 0; p < 8; p++) {
        float e0 = acc[2 * p], e1 = acc[2 * p + 1];
        uint32_t hp = cvt_bf16x2(e1, e0);
        float f0 = __uint_as_float(hp << 16);
        float f1 = __uint_as_float(hp & 0xFFFF0000u);
        ahi[p] = hp;
        alo[p] = cvt_bf16x2(e1 - f1, e0 - f0);
    }
}

__global__ __launch_bounds__(NTHREADS, 2)
void actuator_hmma_kernel(const float* __restrict__ x,
                          const float* __restrict__ W1,
                          const float* __restrict__ b1,
                          const float* __restrict__ Wh,
                          const float* __restrict__ bh,
                          const float* __restrict__ Wout,
                          const float* __restrict__ bout,
                          float* __restrict__ out,
                          int B, int npairs)
{
    extern __shared__ char smem[];
    u64*   sFRAG = (u64*)(smem + SM_FRAG);
    float* sW1   = (float*)(smem + SM_W1);
    float* sB1   = (float*)(smem + SM_B1);
    float* sBH   = (float*)(smem + SM_BH);
    float* sWOUT = (float*)(smem + SM_WOUT);
    float* sBOUT = (float*)(smem + SM_BOUT);

    const int tid = threadIdx.x;

    for (int i = tid; i < 192; i += NTHREADS) sW1[i] = W1[i];
    for (int i = tid; i < 32;  i += NTHREADS) sB1[i] = b1[i];
    for (int i = tid; i < 608; i += NTHREADS) sBH[i] = bh[i];
    for (int i = tid; i < 32;  i += NTHREADS) sWOUT[i] = Wout[i];
    if (tid == 0) sBOUT[0] = bout[0];

    // stage hidden weights as per-thread B fragments (hi & lo)
    // slot = ((l*16 + combo)*32 + lane), combo = term*8 + ks*4 + nb
    for (int idx = tid; idx < 19 * 16 * 32; idx += NTHREADS) {
        int lane  = idx & 31;
        int combo = (idx >> 5) & 15;
        int l     = idx >> 9;
        int nb    = combo & 3;
        int ks    = (combo >> 2) & 1;
        int term  = combo >> 3;
        int col   = nb * 8 + (lane >> 2);
        int qq    = lane & 3;
        int k0    = ks * 16 + qq * 2;

        const float* Wl = Wh + l * 1024;
        float w0 = Wl[(k0 + 0) * 32 + col];
        float w1 = Wl[(k0 + 1) * 32 + col];
        float w2 = Wl[(k0 + 8) * 32 + col];
        float w3 = Wl[(k0 + 9) * 32 + col];

        uint32_t rb0, rb1;
        if (term == 0) {
            rb0 = cvt_bf16x2(w1, w0);
            rb1 = cvt_bf16x2(w3, w2);
        } else {
            float r0 = w0 - __bfloat162float(__float2bfloat16(w0));
            float r1 = w1 - __bfloat162float(__float2bfloat16(w1));
            float r2 = w2 - __bfloat162float(__float2bfloat16(w2));
            float r3 = w3 - __bfloat162float(__float2bfloat16(w3));
            rb0 = cvt_bf16x2(r1, r0);
            rb1 = cvt_bf16x2(r3, r2);
        }
        sFRAG[idx] = ((u64)rb1 << 32) | rb0;
    }
    __syncthreads();

    const int wid  = tid >> 5;
    const int lane = tid & 31;
    const int g    = lane >> 2;
    const int q    = lane & 3;

    const float bias_out = sBOUT[0];

    for (int pair = blockIdx.x * NWARPS + wid; pair < npairs;
         pair += gridDim.x * NWARPS) {

        int base = pair * 32;
        int rA0 = base + g,      rA1 = base + 8 + g;
        int rB0 = base + 16 + g, rB1 = base + 24 + g;
        int cA0 = min(rA0, B - 1), cA1 = min(rA1, B - 1);
        int cB0 = min(rB0, B - 1), cB1 = min(rB1, B - 1);

        float acc0[16], acc1[16];

        // ---- layer 1 (6 -> 32), fp32 SIMT, both tiles ----
        {
            float x0[6], x1[6], x2[6], x3[6];
            const float* p0 = x + (long long)cA0 * 6;
            const float* p1 = x + (long long)cA1 * 6;
            const float* p2 = x + (long long)cB0 * 6;
            const float* p3 = x + (long long)cB1 * 6;
            #pragma unroll
            for (int i = 0; i < 6; i++) {
                x0[i] = __ldg(p0 + i); x1[i] = __ldg(p1 + i);
                x2[i] = __ldg(p2 + i); x3[i] = __ldg(p3 + i);
            }
            #pragma unroll
            for (int nb = 0; nb < 4; nb++) {
                int c0 = nb * 8 + q * 2;
                float b0 = sB1[c0], b1v = sB1[c0 + 1];
                float s00 = b0, s01 = b1v, s10 = b0, s11 = b1v;
                float t00 = b0, t01 = b1v, t10 = b0, t11 = b1v;
                #pragma unroll
                for (int i = 0; i < 6; i++) {
                    float w0 = sW1[i * 32 + c0], w1 = sW1[i * 32 + c0 + 1];
                    s00 += x0[i] * w0; s01 += x0[i] * w1;
                    s10 += x1[i] * w0; s11 += x1[i] * w1;
                    t00 += x2[i] * w0; t01 += x2[i] * w1;
                    t10 += x3[i] * w0; t11 += x3[i] * w1;
                }
                acc0[nb*4+0] = softsign_f(s00); acc0[nb*4+1] = softsign_f(s01);
                acc0[nb*4+2] = softsign_f(s10); acc0[nb*4+3] = softsign_f(s11);
                acc1[nb*4+0] = softsign_f(t00); acc1[nb*4+1] = softsign_f(t01);
                acc1[nb*4+2] = softsign_f(t10); acc1[nb*4+3] = softsign_f(t11);
            }
        }

        // ---- 19 hidden layers via HMMA ----
        for (int l = 0; l < 19; l++) {
            const u64* fl = sFRAG + l * 512 + lane;
            u64 Bf[16];
            #pragma unroll
            for (int c = 0; c < 16; c++) Bf[c] = fl[c * 32];

            uint32_t ahi0[8], alo0[8], ahi1[8], alo1[8];
            split_frags(acc0, ahi0, alo0);
            split_frags(acc1, ahi1, alo1);

            const float2* blp = (const float2*)(sBH + l * 32);
            float2 bb0 = blp[0 * 4 + q];
            float2 bb1 = blp[1 * 4 + q];
            float2 bb2 = blp[2 * 4 + q];
            float2 bb3 = blp[3 * 4 + q];

            #pragma unroll
            for (int ks = 0; ks < 2; ks++) {
                uint32_t a00 = ahi0[ks*4+0], a01 = ahi0[ks*4+1],
                         a02 = ahi0[ks*4+2], a03 = ahi0[ks*4+3];
                uint32_t l00 = alo0[ks*4+0], l01 = alo0[ks*4+1],
                         l02 = alo0[ks*4+2], l03 = alo0[ks*4+3];
                uint32_t a10 = ahi1[ks*4+0], a11 = ahi1[ks*4+1],
                         a12 = ahi1[ks*4+2], a13 = ahi1[ks*4+3];
                uint32_t l10 = alo1[ks*4+0], l11 = alo1[ks*4+1],
                         l12 = alo1[ks*4+2], l13 = alo1[ks*4+3];

                // term 0: hi * Whi
                #pragma unroll
                for (int nb = 0; nb < 4; nb++) {
                    u64 wh = Bf[ks * 4 + nb];
                    uint32_t b0 = (uint32_t)wh, b1v = (uint32_t)(wh >> 32);
                    float* d0 = acc0 + nb * 4;
                    float* d1 = acc1 + nb * 4;
                    if (ks == 0) {
                        float2 bb = (nb == 0) ? bb0 : (nb == 1) ? bb1
                                  : (nb == 2) ? bb2 : bb3;
                        mma_bf16_init(d0, a00, a01, a02, a03, b0, b1v, bb.x, bb.y);
                        mma_bf16_init(d1, a10, a11, a12, a13, b0, b1v, bb.x, bb.y);
                    } else {
                        mma_bf16(d0, a00, a01, a02, a03, b0, b1v);
                        mma_bf16(d1, a10, a11, a12, a13, b0, b1v);
                    }
                }
                // term 1: lo * Whi
                #pragma unroll
                for (int nb = 0; nb < 4; nb++) {
                    u64 wh = Bf[ks * 4 + nb];
                    uint32_t b0 = (uint32_t)wh, b1v = (uint32_t)(wh >> 32);
                    mma_bf16(acc0 + nb * 4, l00, l01, l02, l03, b0, b1v);
                    mma_bf16(acc1 + nb * 4, l10, l11, l12, l13, b0, b1v);
                }
                // term 2: hi * Wlo
                #pragma unroll
                for (int nb = 0; nb < 4; nb++) {
                    u64 wl = Bf[8 + ks * 4 + nb];
                    uint32_t b0 = (uint32_t)wl, b1v = (uint32_t)(wl >> 32);
                    mma_bf16(acc0 + nb * 4, a00, a01, a02, a03, b0, b1v);
                    mma_bf16(acc1 + nb * 4, a10, a11, a12, a13, b0, b1v);
                }
            }

            softsign16_pairwise(acc0);
            softsign16_pairwise(acc1);
        }

        // ---- output layer (32 -> 1) + quad reduction ----
        float pA0 = 0.0f, pA1 = 0.0f, pB0 = 0.0f, pB1 = 0.0f;
        #pragma unroll
        for (int nb = 0; nb < 4; nb++) {
            int c0 = nb * 8 + q * 2;
            float w0 = sWOUT[c0], w1 = sWOUT[c0 + 1];
            pA0 += acc0[nb*4+0] * w0 + acc0[nb*4+1] * w1;
            pA1 += acc0[nb*4+2] * w0 + acc0[nb*4+3] * w1;
            pB0 += acc1[nb*4+0] * w0 + acc1[nb*4+1] * w1;
            pB1 += acc1[nb*4+2] * w0 + acc1[nb*4+3] * w1;
        }
        pA0 += __shfl_xor_sync(0xFFFFFFFFu, pA0, 1);
        pA0 += __shfl_xor_sync(0xFFFFFFFFu, pA0, 2);
        pA1 += __shfl_xor_sync(0xFFFFFFFFu, pA1, 1);
        pA1 += __shfl_xor_sync(0xFFFFFFFFu, pA1, 2);
        pB0 += __shfl_xor_sync(0xFFFFFFFFu, pB0, 1);
        pB0 += __shfl_xor_sync(0xFFFFFFFFu, pB0, 2);
        pB1 += __shfl_xor_sync(0xFFFFFFFFu, pB1, 1);
        pB1 += __shfl_xor_sync(0xFFFFFFFFu, pB1, 2);
        if (q == 0) {
            if (rA0 < B) out[rA0] = pA0 + bias_out;
            if (rA1 < B) out[rA1] = pA1 + bias_out;
            if (rB0 < B) out[rB0] = pB0 + bias_out;
            if (rB1 < B) out[rB1] = pB1 + bias_out;
        }
    }
}

extern "C" void kernel_launch(void* const* d_in, const int* in_sizes, int n_in,
                              void* d_out, int out_size)
{
    const float* x    = (const float*)d_in[0];
    const float* W1   = (const float*)d_in[1];
    const float* b1   = (const float*)d_in[2];
    const float* Wh   = (const float*)d_in[3];
    const float* bh   = (const float*)d_in[4];
    const float* Wout = (const float*)d_in[5];
    const float* bout = (const float*)d_in[6];
    float* out = (float*)d_out;

    int B = in_sizes[0] / 6;
    int npairs = (B + 31) / 32;

    cudaFuncSetAttribute(actuator_hmma_kernel,
                         cudaFuncAttributeMaxDynamicSharedMemorySize, SM_TOTAL);

    int grid = 296;   // persistent: 2 CTAs/SM x 148 SMs
    actuator_hmma_kernel<<<grid, NTHREADS, SM_TOTAL>>>(
        x, W1, b1, Wh, bh, Wout, bout, out, B, npairs);
}

// round 11
// speedup vs baseline: 1.2230x; 1.2230x over previous
#include <cuda_runtime.h>
#include <cuda_bf16.h>
#include <cstdint>

// ActuatorNet via warp-level mma.sync (HMMA, bf16 hi/lo 3-term split).
// Round 11 = round 9 op-set (same issue count!) with cross-tile software
// pipelining: accumulators stay RAW across the layer boundary, and each
// tile's softsign+split (fused) executes while the OTHER tile's MMAs drain.
// Dependent reads of an accumulator now sit ~80-100 issues after the last
// MMA writing it (was ~2 in R9), hiding HMMA latency within one warp.

#define NTHREADS 256
#define NWARPS   8

typedef unsigned long long u64;

// smem layout (bytes)
#define SM_FRAG   0                      // 19*16*32 u64 = 77824
#define SM_W1     77824                  // 192 f32
#define SM_B1     (SM_W1 + 768)          // 32 f32
#define SM_BH     (SM_B1 + 128)          // 19*32 f32 = 2432
#define SM_WOUT   (SM_BH + 2432)         // 32 f32
#define SM_BOUT   (SM_WOUT + 128)        // 1 f32
#define SM_TOTAL  (SM_BOUT + 16)         // ~81.2 KB -> 2 CTAs/SM

__device__ __forceinline__ uint32_t cvt_bf16x2(float hi_elem, float lo_elem) {
    uint32_t r;
    asm("cvt.rn.bf16x2.f32 %0, %1, %2;" : "=r"(r) : "f"(hi_elem), "f"(lo_elem));
    return r;
}

// d += a*b
__device__ __forceinline__ void mma_bf16(float* d,
                                         uint32_t a0, uint32_t a1,
                                         uint32_t a2, uint32_t a3,
                                         uint32_t b0, uint32_t b1) {
    asm volatile(
        "mma.sync.aligned.m16n8k16.row.col.f32.bf16.bf16.f32 "
        "{%0,%1,%2,%3}, {%4,%5,%6,%7}, {%8,%9}, {%0,%1,%2,%3};"
        : "+f"(d[0]), "+f"(d[1]), "+f"(d[2]), "+f"(d[3])
        : "r"(a0), "r"(a1), "r"(a2), "r"(a3), "r"(b0), "r"(b1));
}

// d = a*b + {cx,cy,cx,cy}
__device__ __forceinline__ void mma_bf16_init(float* d,
                                              uint32_t a0, uint32_t a1,
                                              uint32_t a2, uint32_t a3,
                                              uint32_t b0, uint32_t b1,
                                              float cx, float cy) {
    asm volatile(
        "mma.sync.aligned.m16n8k16.row.col.f32.bf16.bf16.f32 "
        "{%0,%1,%2,%3}, {%4,%5,%6,%7}, {%8,%9}, {%10,%11,%10,%11};"
        : "=f"(d[0]), "=f"(d[1]), "=f"(d[2]), "=f"(d[3])
        : "r"(a0), "r"(a1), "r"(a2), "r"(a3), "r"(b0), "r"(b1),
          "f"(cx), "f"(cy));
}

__device__ __forceinline__ float softsign_f(float v) {
    return __fdividef(v, 1.0f + fabsf(v));
}

// fused: y = softsign(raw acc), then split y into bf16 hi/lo A fragments.
// acc is left holding the softsigned activations (needed only after the
// final layer; intermediate layers never read acc again before MMA C-init).
__device__ __forceinline__ void ss_split(float* acc,
                                         uint32_t* ahi, uint32_t* alo) {
    #pragma unroll
    for (int p = 0; p < 8; p++) {
        float e0 = softsign_f(acc[2 * p]);
        float e1 = softsign_f(acc[2 * p + 1]);
        acc[2 * p] = e0; acc[2 * p + 1] = e1;
        uint32_t hp = cvt_bf16x2(e1, e0);
        float f0 = __uint_as_float(hp << 16);
        float f1 = __uint_as_float(hp & 0xFFFF0000u);
        ahi[p] = hp;
        alo[p] = cvt_bf16x2(e1 - f1, e0 - f0);
    }
}

// 24 MMAs for one tile: term-major (dependent spacing 4), bias via C operand.
__device__ __forceinline__ void mma_tile(float* acc, const u64* Bf,
                                         const uint32_t* ahi, const uint32_t* alo,
                                         float2 bb0, float2 bb1,
                                         float2 bb2, float2 bb3) {
    // term 0, ks 0: hi*Whi with bias init
    #pragma unroll
    for (int nb = 0; nb < 4; nb++) {
        u64 w = Bf[nb];
        float2 bb = (nb == 0) ? bb0 : (nb == 1) ? bb1 : (nb == 2) ? bb2 : bb3;
        mma_bf16_init(acc + nb * 4, ahi[0], ahi[1], ahi[2], ahi[3],
                      (uint32_t)w, (uint32_t)(w >> 32), bb.x, bb.y);
    }
    // term 0, ks 1: hi*Whi accumulate
    #pragma unroll
    for (int nb = 0; nb < 4; nb++) {
        u64 w = Bf[4 + nb];
        mma_bf16(acc + nb * 4, ahi[4], ahi[5], ahi[6], ahi[7],
                 (uint32_t)w, (uint32_t)(w >> 32));
    }
    // term 1: lo*Whi (ks 0, ks 1)
    #pragma unroll
    for (int nb = 0; nb < 4; nb++) {
        u64 w = Bf[nb];
        mma_bf16(acc + nb * 4, alo[0], alo[1], alo[2], alo[3],
                 (uint32_t)w, (uint32_t)(w >> 32));
    }
    #pragma unroll
    for (int nb = 0; nb < 4; nb++) {
        u64 w = Bf[4 + nb];
        mma_bf16(acc + nb * 4, alo[4], alo[5], alo[6], alo[7],
                 (uint32_t)w, (uint32_t)(w >> 32));
    }
    // term 2: hi*Wlo (ks 0, ks 1)
    #pragma unroll
    for (int nb = 0; nb < 4; nb++) {
        u64 w = Bf[8 + nb];
        mma_bf16(acc + nb * 4, ahi[0], ahi[1], ahi[2], ahi[3],
                 (uint32_t)w, (uint32_t)(w >> 32));
    }
    #pragma unroll
    for (int nb = 0; nb < 4; nb++) {
        u64 w = Bf[12 + nb];
        mma_bf16(acc + nb * 4, ahi[4], ahi[5], ahi[6], ahi[7],
                 (uint32_t)w, (uint32_t)(w >> 32));
    }
}

__global__ __launch_bounds__(NTHREADS, 2)
void actuator_hmma_kernel(const float* __restrict__ x,
                          const float* __restrict__ W1,
                          const float* __restrict__ b1,
                          const float* __restrict__ Wh,
                          const float* __restrict__ bh,
                          const float* __restrict__ Wout,
                          const float* __restrict__ bout,
                          float* __restrict__ out,
                          int B, int npairs)
{
    extern __shared__ char smem[];
    u64*   sFRAG = (u64*)(smem + SM_FRAG);
    float* sW1   = (float*)(smem + SM_W1);
    float* sB1   = (float*)(smem + SM_B1);
    float* sBH   = (float*)(smem + SM_BH);
    float* sWOUT = (float*)(smem + SM_WOUT);
    float* sBOUT = (float*)(smem + SM_BOUT);

    const int tid = threadIdx.x;

    for (int i = tid; i < 192; i += NTHREADS) sW1[i] = W1[i];
    for (int i = tid; i < 32;  i += NTHREADS) sB1[i] = b1[i];
    for (int i = tid; i < 608; i += NTHREADS) sBH[i] = bh[i];
    for (int i = tid; i < 32;  i += NTHREADS) sWOUT[i] = Wout[i];
    if (tid == 0) sBOUT[0] = bout[0];

    // stage hidden weights as per-thread B fragments (hi & lo)
    // slot = ((l*16 + combo)*32 + lane), combo = term*8 + ks*4 + nb
    for (int idx = tid; idx < 19 * 16 * 32; idx += NTHREADS) {
        int lane  = idx & 31;
        int combo = (idx >> 5) & 15;
        int l     = idx >> 9;
        int nb    = combo & 3;
        int ks    = (combo >> 2) & 1;
        int term  = combo >> 3;
        int col   = nb * 8 + (lane >> 2);
        int qq    = lane & 3;
        int k0    = ks * 16 + qq * 2;

        const float* Wl = Wh + l * 1024;
        float w0 = Wl[(k0 + 0) * 32 + col];
        float w1 = Wl[(k0 + 1) * 32 + col];
        float w2 = Wl[(k0 + 8) * 32 + col];
        float w3 = Wl[(k0 + 9) * 32 + col];

        uint32_t rb0, rb1;
        if (term == 0) {
            rb0 = cvt_bf16x2(w1, w0);
            rb1 = cvt_bf16x2(w3, w2);
        } else {
            float r0 = w0 - __bfloat162float(__float2bfloat16(w0));
            float r1 = w1 - __bfloat162float(__float2bfloat16(w1));
            float r2 = w2 - __bfloat162float(__float2bfloat16(w2));
            float r3 = w3 - __bfloat162float(__float2bfloat16(w3));
            rb0 = cvt_bf16x2(r1, r0);
            rb1 = cvt_bf16x2(r3, r2);
        }
        sFRAG[idx] = ((u64)rb1 << 32) | rb0;
    }
    __syncthreads();

    const int wid  = tid >> 5;
    const int lane = tid & 31;
    const int g    = lane >> 2;
    const int q    = lane & 3;

    const float bias_out = sBOUT[0];

    for (int pair = blockIdx.x * NWARPS + wid; pair < npairs;
         pair += gridDim.x * NWARPS) {

        int base = pair * 32;
        int rA0 = base + g,      rA1 = base + 8 + g;
        int rB0 = base + 16 + g, rB1 = base + 24 + g;
        int cA0 = min(rA0, B - 1), cA1 = min(rA1, B - 1);
        int cB0 = min(rB0, B - 1), cB1 = min(rB1, B - 1);

        // acc holds RAW pre-activations at loop boundaries; softsign is
        // fused into the split at the top of each layer.
        float acc0[16], acc1[16];

        // ---- layer 1 (6 -> 32), fp32 SIMT: leave RAW preactivations ----
        {
            float x0[6], x1[6], x2[6], x3[6];
            const float* p0 = x + (long long)cA0 * 6;
            const float* p1 = x + (long long)cA1 * 6;
            const float* p2 = x + (long long)cB0 * 6;
            const float* p3 = x + (long long)cB1 * 6;
            #pragma unroll
            for (int i = 0; i < 6; i++) {
                x0[i] = __ldg(p0 + i); x1[i] = __ldg(p1 + i);
                x2[i] = __ldg(p2 + i); x3[i] = __ldg(p3 + i);
            }
            #pragma unroll
            for (int nb = 0; nb < 4; nb++) {
                int c0 = nb * 8 + q * 2;
                float b0 = sB1[c0], b1v = sB1[c0 + 1];
                float s00 = b0, s01 = b1v, s10 = b0, s11 = b1v;
                float t00 = b0, t01 = b1v, t10 = b0, t11 = b1v;
                #pragma unroll
                for (int i = 0; i < 6; i++) {
                    float w0 = sW1[i * 32 + c0], w1 = sW1[i * 32 + c0 + 1];
                    s00 += x0[i] * w0; s01 += x0[i] * w1;
                    s10 += x1[i] * w0; s11 += x1[i] * w1;
                    t00 += x2[i] * w0; t01 += x2[i] * w1;
                    t10 += x3[i] * w0; t11 += x3[i] * w1;
                }
                acc0[nb*4+0] = s00; acc0[nb*4+1] = s01;
                acc0[nb*4+2] = s10; acc0[nb*4+3] = s11;
                acc1[nb*4+0] = t00; acc1[nb*4+1] = t01;
                acc1[nb*4+2] = t10; acc1[nb*4+3] = t11;
            }
        }

        // ---- 19 hidden layers, pipelined across the two tiles ----
        for (int l = 0; l < 19; l++) {
            const u64* fl = sFRAG + l * 512 + lane;
            u64 Bf[16];
            #pragma unroll
            for (int c = 0; c < 16; c++) Bf[c] = fl[c * 32];

            const float2* blp = (const float2*)(sBH + l * 32);
            float2 bb0 = blp[0 * 4 + q];
            float2 bb1 = blp[1 * 4 + q];
            float2 bb2 = blp[2 * 4 + q];
            float2 bb3 = blp[3 * 4 + q];

            // tile0 epilogue (shadows tile1's MMAs from layer l-1)
            uint32_t ahi0[8], alo0[8];
            ss_split(acc0, ahi0, alo0);
            mma_tile(acc0, Bf, ahi0, alo0, bb0, bb1, bb2, bb3);

            // tile1 epilogue (shadows tile0's MMAs just issued)
            uint32_t ahi1[8], alo1[8];
            ss_split(acc1, ahi1, alo1);
            mma_tile(acc1, Bf, ahi1, alo1, bb0, bb1, bb2, bb3);
        }

        // ---- final softsign + output layer (32 -> 1) + quad reduction ----
        float pA0 = 0.0f, pA1 = 0.0f, pB0 = 0.0f, pB1 = 0.0f;
        #pragma unroll
        for (int nb = 0; nb < 4; nb++) {
            int c0 = nb * 8 + q * 2;
            float w0 = sWOUT[c0], w1 = sWOUT[c0 + 1];
            pA0 += softsign_f(acc0[nb*4+0]) * w0 + softsign_f(acc0[nb*4+1]) * w1;
            pA1 += softsign_f(acc0[nb*4+2]) * w0 + softsign_f(acc0[nb*4+3]) * w1;
            pB0 += softsign_f(acc1[nb*4+0]) * w0 + softsign_f(acc1[nb*4+1]) * w1;
            pB1 += softsign_f(acc1[nb*4+2]) * w0 + softsign_f(acc1[nb*4+3]) * w1;
        }
        pA0 += __shfl_xor_sync(0xFFFFFFFFu, pA0, 1);
        pA0 += __shfl_xor_sync(0xFFFFFFFFu, pA0, 2);
        pA1 += __shfl_xor_sync(0xFFFFFFFFu, pA1, 1);
        pA1 += __shfl_xor_sync(0xFFFFFFFFu, pA1, 2);
        pB0 += __shfl_xor_sync(0xFFFFFFFFu, pB0, 1);
        pB0 += __shfl_xor_sync(0xFFFFFFFFu, pB0, 2);
        pB1 += __shfl_xor_sync(0xFFFFFFFFu, pB1, 1);
        pB1 += __shfl_xor_sync(0xFFFFFFFFu, pB1, 2);
        if (q == 0) {
            if (rA0 < B) out[rA0] = pA0 + bias_out;
            if (rA1 < B) out[rA1] = pA1 + bias_out;
            if (rB0 < B) out[rB0] = pB0 + bias_out;
            if (rB1 < B) out[rB1] = pB1 + bias_out;
        }
    }
}

extern "C" void kernel_launch(void* const* d_in, const int* in_sizes, int n_in,
                              void* d_out, int out_size)
{
    const float* x    = (const float*)d_in[0];
    const float* W1   = (const float*)d_in[1];
    const float* b1   = (const float*)d_in[2];
    const float* Wh   = (const float*)d_in[3];
    const float* bh   = (const float*)d_in[4];
    const float* Wout = (const float*)d_in[5];
    const float* bout = (const float*)d_in[6];
    float* out = (float*)d_out;

    int B = in_sizes[0] / 6;
    int npairs = (B + 31) / 32;

    cudaFuncSetAttribute(actuator_hmma_kernel,
                         cudaFuncAttributeMaxDynamicSharedMemorySize, SM_TOTAL);

    int grid = 296;   // persistent: 2 CTAs/SM x 148 SMs
    actuator_hmma_kernel<<<grid, NTHREADS, SM_TOTAL>>>(
        x, W1, b1, Wh, bh, Wout, bout, out, B, npairs);
}